// round 1
// baseline (speedup 1.0000x reference)
#include <cuda_runtime.h>
#include <cstdint>

#define N_ROWS 32768
#define D_DIM  512
#define K_CODES 8192

// Scratch (device globals — no allocation allowed in kernel_launch)
__device__ float g_zn[N_ROWS * D_DIM];              // 64 MB normalized z
__device__ float g_cn[K_CODES * D_DIM];             // 16 MB normalized codebook
__device__ unsigned long long g_best[N_ROWS];       // packed (sortable_sim<<32)|~col
__device__ float g_loss;

// ---------------------------------------------------------------------------
// Pack a float similarity + column index into a 64-bit sortable key.
// Higher similarity wins; on exact ties, smaller column index wins
// (matches jnp.argmax first-occurrence semantics) because we store ~col.
// ---------------------------------------------------------------------------
__device__ __forceinline__ unsigned long long pack_key(float v, int col) {
    unsigned u = __float_as_uint(v);
    u = (u & 0x80000000u) ? ~u : (u | 0x80000000u);   // monotone float->uint
    return ((unsigned long long)u << 32) | (unsigned)(~col);
}

// ---------------------------------------------------------------------------
// Init: zero argmax keys and loss accumulator
// ---------------------------------------------------------------------------
__global__ void init_kernel() {
    int i = blockIdx.x * blockDim.x + threadIdx.x;
    if (i < N_ROWS) g_best[i] = 0ull;
    if (i == 0) g_loss = 0.0f;
}

// ---------------------------------------------------------------------------
// Row L2-normalize: out = x / max(||x||, 1e-12). One block (128 thr) per row.
// ---------------------------------------------------------------------------
__global__ void normalize_rows(const float* __restrict__ in, float* __restrict__ out) {
    int row = blockIdx.x;
    const float4* ip = (const float4*)(in + (size_t)row * D_DIM);
    float4 v = ip[threadIdx.x];                        // 128 * 4 = 512
    float ss = v.x * v.x + v.y * v.y + v.z * v.z + v.w * v.w;
    #pragma unroll
    for (int o = 16; o; o >>= 1) ss += __shfl_xor_sync(0xffffffffu, ss, o);
    __shared__ float ws[4];
    if ((threadIdx.x & 31) == 0) ws[threadIdx.x >> 5] = ss;
    __syncthreads();
    float tot = ws[0] + ws[1] + ws[2] + ws[3];
    float inv = 1.0f / fmaxf(sqrtf(tot), 1e-12f);
    float4 o4 = make_float4(v.x * inv, v.y * inv, v.z * inv, v.w * inv);
    ((float4*)(out + (size_t)row * D_DIM))[threadIdx.x] = o4;
}

// ---------------------------------------------------------------------------
// Fused SGEMM + per-row argmax.
// Tile: 128 rows (z) x 128 cols (codes), 256 threads, 8x8 micro-tile, BK=16.
// Epilogue reduces argmax within the CTA (shared atomicMax on packed keys),
// then merges into g_best with global atomicMax.
// ---------------------------------------------------------------------------
__global__ __launch_bounds__(256, 2) void gemm_argmax() {
    __shared__ float As[16][128];
    __shared__ float Bs[16][128];
    __shared__ unsigned long long sbest[128];

    const int tid = threadIdx.x;
    const int tx = tid & 15;          // 0..15 -> col groups of 8
    const int ty = tid >> 4;          // 0..15 -> row groups of 8
    const int rowBase = blockIdx.y * 128;
    const int colBase = blockIdx.x * 128;

    if (tid < 128) sbest[tid] = 0ull;

    float acc[8][8];
    #pragma unroll
    for (int i = 0; i < 8; ++i)
        #pragma unroll
        for (int j = 0; j < 8; ++j) acc[i][j] = 0.0f;

    for (int d0 = 0; d0 < D_DIM; d0 += 16) {
        // Stage A (zn) and B (cn) panels: 128 rows x 16 k, float4 loads
        #pragma unroll
        for (int t = 0; t < 2; ++t) {
            int s = tid + t * 256;          // 0..511
            int r = s >> 2;
            int kq = (s & 3) << 2;
            float4 a = *(const float4*)(&g_zn[(size_t)(rowBase + r) * D_DIM + d0 + kq]);
            As[kq + 0][r] = a.x; As[kq + 1][r] = a.y; As[kq + 2][r] = a.z; As[kq + 3][r] = a.w;
            float4 b = *(const float4*)(&g_cn[(size_t)(colBase + r) * D_DIM + d0 + kq]);
            Bs[kq + 0][r] = b.x; Bs[kq + 1][r] = b.y; Bs[kq + 2][r] = b.z; Bs[kq + 3][r] = b.w;
        }
        __syncthreads();

        #pragma unroll
        for (int k = 0; k < 16; ++k) {
            float a[8], b[8];
            #pragma unroll
            for (int i = 0; i < 8; ++i) a[i] = As[k][ty * 8 + i];
            #pragma unroll
            for (int j = 0; j < 8; ++j) b[j] = Bs[k][tx * 8 + j];
            #pragma unroll
            for (int i = 0; i < 8; ++i)
                #pragma unroll
                for (int j = 0; j < 8; ++j)
                    acc[i][j] = fmaf(a[i], b[j], acc[i][j]);
        }
        __syncthreads();
    }

    // Per-thread argmax over its 8 columns, per row; ascending j keeps first idx
    #pragma unroll
    for (int i = 0; i < 8; ++i) {
        float bv = acc[i][0];
        int bj = 0;
        #pragma unroll
        for (int j = 1; j < 8; ++j)
            if (acc[i][j] > bv) { bv = acc[i][j]; bj = j; }
        atomicMax(&sbest[ty * 8 + i], pack_key(bv, colBase + tx * 8 + bj));
    }
    __syncthreads();
    if (tid < 128) atomicMax(&g_best[rowBase + tid], sbest[tid]);
}

// ---------------------------------------------------------------------------
// Output: zq row = cn[idx] (identical computation to normalize(codebook[idx])),
// indices (as float if slot present), and loss partials.
// One block (128 thr) per row.
// ---------------------------------------------------------------------------
__global__ void output_kernel(float* __restrict__ zq, float* __restrict__ idx_out,
                              int do_loss) {
    int n = blockIdx.x;
    unsigned long long key = g_best[n];
    int idx = (int)(~(unsigned)key);

    float4 cv = ((const float4*)(&g_cn[(size_t)idx * D_DIM]))[threadIdx.x];
    float4 zv = ((const float4*)(&g_zn[(size_t)n * D_DIM]))[threadIdx.x];
    ((float4*)(zq + (size_t)n * D_DIM))[threadIdx.x] = cv;

    if (idx_out && threadIdx.x == 0) idx_out[n] = (float)idx;

    if (do_loss) {
        float dx = cv.x - zv.x, dy = cv.y - zv.y, dz = cv.z - zv.z, dw = cv.w - zv.w;
        float ss = dx * dx + dy * dy + dz * dz + dw * dw;
        #pragma unroll
        for (int o = 16; o; o >>= 1) ss += __shfl_xor_sync(0xffffffffu, ss, o);
        __shared__ float ws[4];
        if ((threadIdx.x & 31) == 0) ws[threadIdx.x >> 5] = ss;
        __syncthreads();
        if (threadIdx.x == 0)
            atomicAdd(&g_loss, ws[0] + ws[1] + ws[2] + ws[3]);
    }
}

__global__ void finalize_kernel(float* __restrict__ loss_slot) {
    // loss = beta*mean + mean = 1.5 * mean((zq - zn)^2)
    *loss_slot = 1.5f * g_loss / 16777216.0f;   // N*D = 32768*512
}

// ---------------------------------------------------------------------------
extern "C" void kernel_launch(void* const* d_in, const int* in_sizes, int n_in,
                              void* d_out, int out_size) {
    const float* z = (const float*)d_in[0];        // [N, D]
    const float* codebook = (const float*)d_in[1]; // [K, D]
    float* out = (float*)d_out;

    const long long ND = (long long)N_ROWS * D_DIM;
    float* zq = out;
    float* idx_out = (out_size >= ND + N_ROWS) ? (out + ND) : nullptr;
    float* loss_slot = (out_size >= ND + N_ROWS + 1) ? (out + ND + N_ROWS) : nullptr;

    init_kernel<<<(N_ROWS + 255) / 256, 256>>>();
    {
        float* zn; cudaGetSymbolAddress((void**)&zn, g_zn);
        float* cn; cudaGetSymbolAddress((void**)&cn, g_cn);
        normalize_rows<<<N_ROWS, 128>>>(z, zn);
        normalize_rows<<<K_CODES, 128>>>(codebook, cn);
    }
    dim3 grid(K_CODES / 128, N_ROWS / 128);   // (64, 256)
    gemm_argmax<<<grid, 256>>>();
    output_kernel<<<N_ROWS, 128>>>(zq, idx_out, loss_slot != nullptr);
    if (loss_slot) finalize_kernel<<<1, 1>>>(loss_slot);
}

// round 5
// speedup vs baseline: 4.2303x; 4.2303x over previous
#include <cuda_runtime.h>
#include <cuda_bf16.h>
#include <cstdint>

#define N_ROWS  32768
#define D_DIM   512
#define K_CODES 8192
#define CAP     64
// Worst-case bf16 screening error bound: 2 * 2^-8 = 7.8e-3. EPS must exceed it.
#define EPS_MARGIN 1.25e-2f

// ---------------------------------------------------------------------------
// Device scratch
// ---------------------------------------------------------------------------
__device__ float          g_zn[N_ROWS  * D_DIM];   // 64 MB normalized z (fp32)
__device__ float          g_cn[K_CODES * D_DIM];   // 16 MB normalized codebook (fp32)
__device__ __nv_bfloat16  g_zb[N_ROWS  * D_DIM];   // 32 MB bf16 zn
__device__ __nv_bfloat16  g_cb[K_CODES * D_DIM];   //  8 MB bf16 cn
__device__ int            g_cand[N_ROWS][CAP];     //  8 MB candidate cols
__device__ int            g_candcnt[N_ROWS];
__device__ float          g_loss;

// ---------------------------------------------------------------------------
// Helpers
// ---------------------------------------------------------------------------
__device__ __forceinline__ uint32_t smem_u32(const void* p) {
    uint32_t a;
    asm("{ .reg .u64 t; cvta.to.shared.u64 t, %1; cvt.u32.u64 %0, t; }"
        : "=r"(a) : "l"(p));
    return a;
}
#define SWZ(o) ((o) ^ (((o) >> 3) & 0x70))

__device__ __forceinline__ void cp_async16(uint32_t dst, const void* src) {
    asm volatile("cp.async.cg.shared.global [%0], [%1], 16;"
                 :: "r"(dst), "l"(src) : "memory");
}
#define CP_COMMIT() asm volatile("cp.async.commit_group;" ::: "memory")
#define CP_WAIT1()  asm volatile("cp.async.wait_group 1;" ::: "memory")
#define CP_WAIT0()  asm volatile("cp.async.wait_group 0;" ::: "memory")

__device__ __forceinline__ void ldsm_x4(uint32_t* r, uint32_t addr) {
    asm volatile("ldmatrix.sync.aligned.m8n8.x4.shared.b16 {%0,%1,%2,%3}, [%4];"
                 : "=r"(r[0]), "=r"(r[1]), "=r"(r[2]), "=r"(r[3]) : "r"(addr));
}
__device__ __forceinline__ void mma_bf16(float* c, const uint32_t* a,
                                         uint32_t b0, uint32_t b1) {
    asm volatile(
        "mma.sync.aligned.m16n8k16.row.col.f32.bf16.bf16.f32 "
        "{%0,%1,%2,%3}, {%4,%5,%6,%7}, {%8,%9}, {%0,%1,%2,%3};"
        : "+f"(c[0]), "+f"(c[1]), "+f"(c[2]), "+f"(c[3])
        : "r"(a[0]), "r"(a[1]), "r"(a[2]), "r"(a[3]), "r"(b0), "r"(b1));
}

// monotone float <-> uint (order-preserving)
__device__ __forceinline__ uint32_t mono(float v) {
    uint32_t u = __float_as_uint(v);
    return (u & 0x80000000u) ? ~u : (u | 0x80000000u);
}
__device__ __forceinline__ float unmono(uint32_t u) {
    return __uint_as_float((u & 0x80000000u) ? (u & 0x7fffffffu) : ~u);
}
__device__ __forceinline__ unsigned long long pack_key(float v, int col) {
    return ((unsigned long long)mono(v) << 32) | (unsigned)(~col);
}

// Sequential-order exact fp32 dot: single accumulator, k ascending (matches
// the R1 kernel whose indices agreed with the reference on every row).
__device__ __forceinline__ float dot_seq(const float* __restrict__ a,
                                         const float* __restrict__ b) {
    float s = 0.0f;
    #pragma unroll 16
    for (int q = 0; q < D_DIM / 4; ++q) {
        float4 av = ((const float4*)a)[q];
        float4 bv = ((const float4*)b)[q];
        s = fmaf(av.x, bv.x, s);
        s = fmaf(av.y, bv.y, s);
        s = fmaf(av.z, bv.z, s);
        s = fmaf(av.w, bv.w, s);
    }
    return s;
}

// ---------------------------------------------------------------------------
__global__ void init_kernel() {
    int i = blockIdx.x * blockDim.x + threadIdx.x;
    if (i < N_ROWS) g_candcnt[i] = 0;
    if (i == 0) g_loss = 0.0f;
}

// Row L2-normalize -> fp32 + bf16. One block (128 thr) per row.
__global__ void normalize_rows(const float* __restrict__ in,
                               float* __restrict__ out_f,
                               __nv_bfloat16* __restrict__ out_b) {
    int row = blockIdx.x;
    float4 v = ((const float4*)(in + (size_t)row * D_DIM))[threadIdx.x];
    float ss = v.x * v.x + v.y * v.y + v.z * v.z + v.w * v.w;
    #pragma unroll
    for (int o = 16; o; o >>= 1) ss += __shfl_xor_sync(0xffffffffu, ss, o);
    __shared__ float ws[4];
    if ((threadIdx.x & 31) == 0) ws[threadIdx.x >> 5] = ss;
    __syncthreads();
    float inv = 1.0f / fmaxf(sqrtf(ws[0] + ws[1] + ws[2] + ws[3]), 1e-12f);
    float4 o4 = make_float4(v.x * inv, v.y * inv, v.z * inv, v.w * inv);
    ((float4*)(out_f + (size_t)row * D_DIM))[threadIdx.x] = o4;
    __nv_bfloat162 b0 = __floats2bfloat162_rn(o4.x, o4.y);
    __nv_bfloat162 b1 = __floats2bfloat162_rn(o4.z, o4.w);
    ((uint2*)(out_b + (size_t)row * D_DIM))[threadIdx.x] =
        make_uint2(*(uint32_t*)&b0, *(uint32_t*)&b1);
}

// ---------------------------------------------------------------------------
// HMMA bf16 screening GEMM + prefix-max candidate collection.
// CTA = 128 z-rows, 512 threads (16 warps, 4x4), warp tile 32x32.
// A (128x512 bf16, chunk-major [8][128][64]) resident in SMEM.
// Loops 64 N-tiles of 128 codes; per tile K streamed in 8 chunks of 64,
// double-buffered cp.async.
// ---------------------------------------------------------------------------
#define SMEM_A    0           // 8 chunks * 16384 = 131072
#define SMEM_B    131072      // 2 bufs * 16384 = 32768
#define SMEM_RMAX 163840      // 128 * 4 = 512
#define SMEM_TOT  164352

__global__ __launch_bounds__(512, 1) void gemm_screen() {
    extern __shared__ char smem[];
    const uint32_t sb = smem_u32(smem);
    const int tid = threadIdx.x;
    const int lane = tid & 31;
    const int wid = tid >> 5;
    const int warpM = wid >> 2;      // 0..3
    const int warpN = wid & 3;       // 0..3
    const int rowBase = blockIdx.x * 128;
    uint32_t* srunmax = (uint32_t*)(smem + SMEM_RMAX);

    if (tid < 128) srunmax[tid] = 0u;   // mono(-inf)

    // Stage resident A: 128 rows x 512 bf16, chunk-major, swizzled
    #pragma unroll
    for (int it = 0; it < 16; ++it) {
        int u = tid + it * 512;             // 0..8191 16B-units
        int c  = u >> 10;                   // k-chunk
        int r  = (u >> 3) & 127;
        int cu = u & 7;                     // 16B unit in row
        cp_async16(sb + SMEM_A + c * 16384 + SWZ(r * 128 + cu * 16),
                   &g_zb[(size_t)(rowBase + r) * D_DIM + c * 64 + cu * 8]);
    }
    CP_COMMIT();

    // Prefetch first B chunk (tile 0, chunk 0) into buf 0
    #pragma unroll
    for (int it = 0; it < 2; ++it) {
        int u = tid + it * 512;             // 0..1023
        int r = u >> 3, cu = u & 7;
        cp_async16(sb + SMEM_B + SWZ(r * 128 + cu * 16),
                   &g_cb[(size_t)r * D_DIM + cu * 8]);
    }
    CP_COMMIT();

    float acc[2][4][4];

    for (int cg = 0; cg < 512; ++cg) {       // 64 tiles * 8 chunks
        const int nt = cg >> 3;
        const int c  = cg & 7;
        const int buf = cg & 1;

        if (cg + 1 < 512) {                   // prefetch next chunk
            const int nnt = (cg + 1) >> 3, nc = (cg + 1) & 7;
            const uint32_t dstb = sb + SMEM_B + ((cg + 1) & 1) * 16384;
            #pragma unroll
            for (int it = 0; it < 2; ++it) {
                int u = tid + it * 512;
                int r = u >> 3, cu = u & 7;
                cp_async16(dstb + SWZ(r * 128 + cu * 16),
                           &g_cb[(size_t)(nnt * 128 + r) * D_DIM + nc * 64 + cu * 8]);
            }
            CP_COMMIT();
            CP_WAIT1();
        } else {
            CP_WAIT0();
        }
        __syncthreads();                      // chunk c (all threads) ready

        if (c == 0) {
            #pragma unroll
            for (int m = 0; m < 2; ++m)
                #pragma unroll
                for (int j = 0; j < 4; ++j)
                    #pragma unroll
                    for (int e = 0; e < 4; ++e) acc[m][j][e] = 0.0f;
        }

        const uint32_t Ab = sb + SMEM_A + c * 16384;
        const uint32_t Bb = sb + SMEM_B + buf * 16384;
        const int ra = warpM * 32 + (lane & 15);
        const int ca = (lane >> 4);
        const int nb = warpN * 32 + (lane & 7) + ((lane >> 4) << 3);
        const int cb = (lane >> 3) & 1;

        #pragma unroll
        for (int s = 0; s < 4; ++s) {
            uint32_t a[2][4], b[2][4];
            #pragma unroll
            for (int m = 0; m < 2; ++m)
                ldsm_x4(a[m], Ab + SWZ((ra + m * 16) * 128 + (s * 2 + ca) * 16));
            #pragma unroll
            for (int p = 0; p < 2; ++p)
                ldsm_x4(b[p], Bb + SWZ((nb + p * 16) * 128 + (s * 2 + cb) * 16));
            #pragma unroll
            for (int m = 0; m < 2; ++m)
                #pragma unroll
                for (int j = 0; j < 4; ++j)
                    mma_bf16(acc[m][j], a[m],
                             b[j >> 1][(j & 1) * 2], b[j >> 1][(j & 1) * 2 + 1]);
        }
        __syncthreads();     // all reads of buf done before it is re-filled

        if (c == 7) {
            // ---- epilogue for tile nt: prefix-max + candidate emission ----
            const int g = lane >> 2, tg = lane & 3;
            #pragma unroll
            for (int m = 0; m < 2; ++m)
                #pragma unroll
                for (int h = 0; h < 2; ++h) {
                    int row = warpM * 32 + m * 16 + h * 8 + g;
                    float mx = -1e30f;
                    #pragma unroll
                    for (int j = 0; j < 4; ++j)
                        mx = fmaxf(mx, fmaxf(acc[m][j][h * 2], acc[m][j][h * 2 + 1]));
                    mx = fmaxf(mx, __shfl_xor_sync(0xffffffffu, mx, 1));
                    mx = fmaxf(mx, __shfl_xor_sync(0xffffffffu, mx, 2));
                    if (tg == 0) atomicMax(&srunmax[row], mono(mx));
                }
            __syncthreads();
            #pragma unroll
            for (int m = 0; m < 2; ++m)
                #pragma unroll
                for (int h = 0; h < 2; ++h) {
                    int row = warpM * 32 + m * 16 + h * 8 + g;
                    float thr = unmono(srunmax[row]) - EPS_MARGIN;
                    #pragma unroll
                    for (int j = 0; j < 4; ++j)
                        #pragma unroll
                        for (int e = 0; e < 2; ++e) {
                            float v = acc[m][j][h * 2 + e];
                            if (v >= thr) {
                                int col = nt * 128 + warpN * 32 + j * 8 + 2 * tg + e;
                                int pos = atomicAdd(&g_candcnt[rowBase + row], 1);
                                if (pos < CAP) g_cand[rowBase + row][pos] = col;
                            }
                        }
                }
            __syncthreads();
        }
    }
}

// ---------------------------------------------------------------------------
// Exact fp32 rescoring of candidates + outputs + loss. One block per row.
// Rescore dots use the sequential ascending-k single-accumulator order that
// matched the reference argmax on every row in the R1 all-fp32 kernel.
// ---------------------------------------------------------------------------
__global__ void finalize_rows(float* __restrict__ zq, float* __restrict__ idx_out,
                              int do_loss) {
    const int n = blockIdx.x;
    const int tid = threadIdx.x;
    const int w = tid >> 5, l = tid & 31;
    __shared__ unsigned long long sbest;
    __shared__ float ws[4];
    if (tid == 0) sbest = 0ull;
    __syncthreads();

    const float* zrow = g_zn + (size_t)n * D_DIM;
    int cnt = g_candcnt[n];

    if (cnt <= CAP) {
        // one thread per candidate, sequential-order dot
        if (tid < cnt) {
            int col = g_cand[n][tid];
            float s = dot_seq(zrow, g_cn + (size_t)col * D_DIM);
            atomicMax(&sbest, pack_key(s, col));
        }
    } else {
        // overflow fallback (should not happen): exact scan of all codes,
        // same sequential per-dot order
        for (int col = tid; col < K_CODES; col += 128) {
            float s = dot_seq(zrow, g_cn + (size_t)col * D_DIM);
            atomicMax(&sbest, pack_key(s, col));
        }
    }
    __syncthreads();
    int idx = (int)(~(unsigned)sbest);

    float4 cv = ((const float4*)(g_cn + (size_t)idx * D_DIM))[tid];
    float4 zv = ((const float4*)zrow)[tid];
    ((float4*)(zq + (size_t)n * D_DIM))[tid] = cv;
    if (idx_out && tid == 0) idx_out[n] = (float)idx;

    if (do_loss) {
        float dx = cv.x - zv.x, dy = cv.y - zv.y, dz = cv.z - zv.z, dw = cv.w - zv.w;
        float ss = dx * dx + dy * dy + dz * dz + dw * dw;
        #pragma unroll
        for (int o = 16; o; o >>= 1) ss += __shfl_xor_sync(0xffffffffu, ss, o);
        if (l == 0) ws[w] = ss;
        __syncthreads();
        if (tid == 0) atomicAdd(&g_loss, ws[0] + ws[1] + ws[2] + ws[3]);
    }
}

__global__ void finalize_loss(float* __restrict__ loss_slot) {
    *loss_slot = 1.5f * g_loss / 16777216.0f;   // (beta+1) * mean, N*D = 2^24
}

// ---------------------------------------------------------------------------
extern "C" void kernel_launch(void* const* d_in, const int* in_sizes, int n_in,
                              void* d_out, int out_size) {
    const float* z = (const float*)d_in[0];
    const float* codebook = (const float*)d_in[1];
    float* out = (float*)d_out;

    const long long ND = (long long)N_ROWS * D_DIM;
    float* zq = out;
    float* idx_out   = (out_size >= ND + N_ROWS)     ? (out + ND) : nullptr;
    float* loss_slot = (out_size >= ND + N_ROWS + 1) ? (out + ND + N_ROWS) : nullptr;

    cudaFuncSetAttribute(gemm_screen,
                         cudaFuncAttributeMaxDynamicSharedMemorySize, SMEM_TOT);

    float *zn, *cn;
    __nv_bfloat16 *zb, *cb;
    cudaGetSymbolAddress((void**)&zn, g_zn);
    cudaGetSymbolAddress((void**)&cn, g_cn);
    cudaGetSymbolAddress((void**)&zb, g_zb);
    cudaGetSymbolAddress((void**)&cb, g_cb);

    init_kernel<<<(N_ROWS + 255) / 256, 256>>>();
    normalize_rows<<<N_ROWS, 128>>>(z, zn, zb);
    normalize_rows<<<K_CODES, 128>>>(codebook, cn, cb);
    gemm_screen<<<N_ROWS / 128, 512, SMEM_TOT>>>();
    finalize_rows<<<N_ROWS, 128>>>(zq, idx_out, loss_slot != nullptr);
    if (loss_slot) finalize_loss<<<1, 1>>>(loss_slot);
}

// round 6
// speedup vs baseline: 4.3247x; 1.0223x over previous
#include <cuda_runtime.h>
#include <cuda_bf16.h>
#include <cstdint>

#define N_ROWS  32768
#define D_DIM   512
#define K_CODES 8192
#define CAP     64
// Worst-case bf16 screening error bound: 2 * 2^-8 = 7.8e-3. EPS must exceed it.
#define EPS_MARGIN 1.25e-2f

// ---------------------------------------------------------------------------
// Device scratch
// ---------------------------------------------------------------------------
__device__ float          g_zn[N_ROWS  * D_DIM];   // 64 MB normalized z (fp32)
__device__ float          g_cn[K_CODES * D_DIM];   // 16 MB normalized codebook (fp32)
__device__ __nv_bfloat16  g_zb[N_ROWS  * D_DIM];   // 32 MB bf16 zn
__device__ __nv_bfloat16  g_cb[K_CODES * D_DIM];   //  8 MB bf16 cn
__device__ int            g_cand[N_ROWS][CAP];     //  8 MB candidate cols
__device__ int            g_candcnt[N_ROWS];
__device__ float          g_loss;

// ---------------------------------------------------------------------------
// Helpers
// ---------------------------------------------------------------------------
__device__ __forceinline__ uint32_t smem_u32(const void* p) {
    uint32_t a;
    asm("{ .reg .u64 t; cvta.to.shared.u64 t, %1; cvt.u32.u64 %0, t; }"
        : "=r"(a) : "l"(p));
    return a;
}
#define SWZ(o) ((o) ^ (((o) >> 3) & 0x70))

__device__ __forceinline__ void cp_async16(uint32_t dst, const void* src) {
    asm volatile("cp.async.cg.shared.global [%0], [%1], 16;"
                 :: "r"(dst), "l"(src) : "memory");
}
#define CP_COMMIT() asm volatile("cp.async.commit_group;" ::: "memory")
#define CP_WAIT2()  asm volatile("cp.async.wait_group 2;" ::: "memory")

__device__ __forceinline__ void ldsm_x4(uint32_t* r, uint32_t addr) {
    asm volatile("ldmatrix.sync.aligned.m8n8.x4.shared.b16 {%0,%1,%2,%3}, [%4];"
                 : "=r"(r[0]), "=r"(r[1]), "=r"(r[2]), "=r"(r[3]) : "r"(addr));
}
__device__ __forceinline__ void mma_bf16(float* c, const uint32_t* a,
                                         uint32_t b0, uint32_t b1) {
    asm volatile(
        "mma.sync.aligned.m16n8k16.row.col.f32.bf16.bf16.f32 "
        "{%0,%1,%2,%3}, {%4,%5,%6,%7}, {%8,%9}, {%0,%1,%2,%3};"
        : "+f"(c[0]), "+f"(c[1]), "+f"(c[2]), "+f"(c[3])
        : "r"(a[0]), "r"(a[1]), "r"(a[2]), "r"(a[3]), "r"(b0), "r"(b1));
}

// monotone float <-> uint (order-preserving)
__device__ __forceinline__ uint32_t mono(float v) {
    uint32_t u = __float_as_uint(v);
    return (u & 0x80000000u) ? ~u : (u | 0x80000000u);
}
__device__ __forceinline__ float unmono(uint32_t u) {
    return __uint_as_float((u & 0x80000000u) ? (u & 0x7fffffffu) : ~u);
}
__device__ __forceinline__ unsigned long long pack_key(float v, int col) {
    return ((unsigned long long)mono(v) << 32) | (unsigned)(~col);
}

// Sequential-order exact fp32 dot: single accumulator, k ascending (matches
// the R1 kernel whose indices agreed with the reference on every row).
__device__ __forceinline__ float dot_seq(const float* __restrict__ a,
                                         const float* __restrict__ b) {
    float s = 0.0f;
    #pragma unroll 16
    for (int q = 0; q < D_DIM / 4; ++q) {
        float4 av = ((const float4*)a)[q];
        float4 bv = ((const float4*)b)[q];
        s = fmaf(av.x, bv.x, s);
        s = fmaf(av.y, bv.y, s);
        s = fmaf(av.z, bv.z, s);
        s = fmaf(av.w, bv.w, s);
    }
    return s;
}

// ---------------------------------------------------------------------------
__global__ void init_kernel() {
    int i = blockIdx.x * blockDim.x + threadIdx.x;
    if (i < N_ROWS) g_candcnt[i] = 0;
    if (i == 0) g_loss = 0.0f;
}

// Row L2-normalize -> fp32 + bf16. One block (128 thr) per row.
__global__ void normalize_rows(const float* __restrict__ in,
                               float* __restrict__ out_f,
                               __nv_bfloat16* __restrict__ out_b) {
    int row = blockIdx.x;
    float4 v = ((const float4*)(in + (size_t)row * D_DIM))[threadIdx.x];
    float ss = v.x * v.x + v.y * v.y + v.z * v.z + v.w * v.w;
    #pragma unroll
    for (int o = 16; o; o >>= 1) ss += __shfl_xor_sync(0xffffffffu, ss, o);
    __shared__ float ws[4];
    if ((threadIdx.x & 31) == 0) ws[threadIdx.x >> 5] = ss;
    __syncthreads();
    float inv = 1.0f / fmaxf(sqrtf(ws[0] + ws[1] + ws[2] + ws[3]), 1e-12f);
    float4 o4 = make_float4(v.x * inv, v.y * inv, v.z * inv, v.w * inv);
    ((float4*)(out_f + (size_t)row * D_DIM))[threadIdx.x] = o4;
    __nv_bfloat162 b0 = __floats2bfloat162_rn(o4.x, o4.y);
    __nv_bfloat162 b1 = __floats2bfloat162_rn(o4.z, o4.w);
    ((uint2*)(out_b + (size_t)row * D_DIM))[threadIdx.x] =
        make_uint2(*(uint32_t*)&b0, *(uint32_t*)&b1);
}

// ---------------------------------------------------------------------------
// HMMA bf16 screening GEMM + prefix-max candidate collection.
// CTA = 128 z-rows, 512 threads (16 warps, 4x4), warp tile 32x32.
// A (128x512 bf16, chunk-major [8][128][64]) resident in SMEM.
// B: 4-stage ring of 16KB chunks (128 codes x 64 k), prefetch distance 3,
// ONE __syncthreads per chunk. Loops 64 N-tiles x 8 k-chunks.
// ---------------------------------------------------------------------------
#define SMEM_A    0           // 8 chunks * 16384 = 131072
#define SMEM_B    131072      // 4 stages * 16384 = 65536
#define SMEM_RMAX 196608      // 128 * 4 = 512
#define SMEM_TOT  197632

__device__ __forceinline__ void prefetch_b(uint32_t sb, int cg, int tid) {
    const int nt = cg >> 3, c = cg & 7;
    const uint32_t dstb = sb + SMEM_B + (cg & 3) * 16384;
    #pragma unroll
    for (int it = 0; it < 2; ++it) {
        int u = tid + it * 512;             // 0..1023 16B units
        int r = u >> 3, cu = u & 7;
        cp_async16(dstb + SWZ(r * 128 + cu * 16),
                   &g_cb[(size_t)(nt * 128 + r) * D_DIM + c * 64 + cu * 8]);
    }
}

__global__ __launch_bounds__(512, 1) void gemm_screen() {
    extern __shared__ char smem[];
    const uint32_t sb = smem_u32(smem);
    const int tid = threadIdx.x;
    const int lane = tid & 31;
    const int wid = tid >> 5;
    const int warpM = wid >> 2;      // 0..3
    const int warpN = wid & 3;       // 0..3
    const int rowBase = blockIdx.x * 128;
    uint32_t* srunmax = (uint32_t*)(smem + SMEM_RMAX);

    if (tid < 128) srunmax[tid] = 0u;   // mono(-inf)

    // Group 0: resident A (128 rows x 512 bf16, chunk-major, swizzled)
    #pragma unroll
    for (int it = 0; it < 16; ++it) {
        int u = tid + it * 512;             // 0..8191 16B-units
        int c  = u >> 10;                   // k-chunk
        int r  = (u >> 3) & 127;
        int cu = u & 7;                     // 16B unit in row
        cp_async16(sb + SMEM_A + c * 16384 + SWZ(r * 128 + cu * 16),
                   &g_zb[(size_t)(rowBase + r) * D_DIM + c * 64 + cu * 8]);
    }
    CP_COMMIT();

    // Groups 1..3: B stages 0..2
    prefetch_b(sb, 0, tid); CP_COMMIT();
    prefetch_b(sb, 1, tid); CP_COMMIT();
    prefetch_b(sb, 2, tid); CP_COMMIT();

    float acc[2][4][4];

    const int ra = warpM * 32 + (lane & 15);
    const int ca = (lane >> 4);
    const int nb = warpN * 32 + (lane & 7) + ((lane >> 4) << 3);
    const int cb = (lane >> 3) & 1;

    for (int cg = 0; cg < 512; ++cg) {       // 64 tiles * 8 chunks
        const int nt = cg >> 3;
        const int c  = cg & 7;

        // stage cg's group is 3rd-from-newest => wait_group 2 drains it
        CP_WAIT2();
        __syncthreads();
        // safe to overwrite slot (cg+3)&3 == (cg-1)&3: all warps passed the
        // barrier above, so chunk cg-1 compute is complete everywhere.
        if (cg + 3 < 512) prefetch_b(sb, cg + 3, tid);
        CP_COMMIT();                          // uniform one-group-per-iter

        if (c == 0) {
            #pragma unroll
            for (int m = 0; m < 2; ++m)
                #pragma unroll
                for (int j = 0; j < 4; ++j)
                    #pragma unroll
                    for (int e = 0; e < 4; ++e) acc[m][j][e] = 0.0f;
        }

        const uint32_t Ab = sb + SMEM_A + c * 16384;
        const uint32_t Bb = sb + SMEM_B + (cg & 3) * 16384;

        #pragma unroll
        for (int s = 0; s < 4; ++s) {
            uint32_t a[2][4], b[2][4];
            #pragma unroll
            for (int m = 0; m < 2; ++m)
                ldsm_x4(a[m], Ab + SWZ((ra + m * 16) * 128 + (s * 2 + ca) * 16));
            #pragma unroll
            for (int p = 0; p < 2; ++p)
                ldsm_x4(b[p], Bb + SWZ((nb + p * 16) * 128 + (s * 2 + cb) * 16));
            #pragma unroll
            for (int m = 0; m < 2; ++m)
                #pragma unroll
                for (int j = 0; j < 4; ++j)
                    mma_bf16(acc[m][j], a[m],
                             b[j >> 1][(j & 1) * 2], b[j >> 1][(j & 1) * 2 + 1]);
        }

        if (c == 7) {
            // ---- epilogue for tile nt: prefix-max + candidate emission ----
            const int g = lane >> 2, tg = lane & 3;
            #pragma unroll
            for (int m = 0; m < 2; ++m)
                #pragma unroll
                for (int h = 0; h < 2; ++h) {
                    int row = warpM * 32 + m * 16 + h * 8 + g;
                    float mx = -1e30f;
                    #pragma unroll
                    for (int j = 0; j < 4; ++j)
                        mx = fmaxf(mx, fmaxf(acc[m][j][h * 2], acc[m][j][h * 2 + 1]));
                    mx = fmaxf(mx, __shfl_xor_sync(0xffffffffu, mx, 1));
                    mx = fmaxf(mx, __shfl_xor_sync(0xffffffffu, mx, 2));
                    if (tg == 0) atomicMax(&srunmax[row], mono(mx));
                }
            __syncthreads();
            #pragma unroll
            for (int m = 0; m < 2; ++m)
                #pragma unroll
                for (int h = 0; h < 2; ++h) {
                    int row = warpM * 32 + m * 16 + h * 8 + g;
                    float thr = unmono(srunmax[row]) - EPS_MARGIN;
                    #pragma unroll
                    for (int j = 0; j < 4; ++j)
                        #pragma unroll
                        for (int e = 0; e < 2; ++e) {
                            float v = acc[m][j][h * 2 + e];
                            if (v >= thr) {
                                int col = nt * 128 + warpN * 32 + j * 8 + 2 * tg + e;
                                int pos = atomicAdd(&g_candcnt[rowBase + row], 1);
                                if (pos < CAP) g_cand[rowBase + row][pos] = col;
                            }
                        }
                }
        }
    }
}

// ---------------------------------------------------------------------------
// Exact fp32 rescoring of candidates + outputs + loss. One block per row.
// Rescore dots use the sequential ascending-k single-accumulator order that
// matched the reference argmax on every row in the R1 all-fp32 kernel.
// ---------------------------------------------------------------------------
__global__ void finalize_rows(float* __restrict__ zq, float* __restrict__ idx_out,
                              int do_loss) {
    const int n = blockIdx.x;
    const int tid = threadIdx.x;
    const int w = tid >> 5, l = tid & 31;
    __shared__ unsigned long long sbest;
    __shared__ float ws[4];
    if (tid == 0) sbest = 0ull;
    __syncthreads();

    const float* zrow = g_zn + (size_t)n * D_DIM;
    int cnt = g_candcnt[n];

    if (cnt <= CAP) {
        // one thread per candidate, sequential-order dot
        if (tid < cnt) {
            int col = g_cand[n][tid];
            float s = dot_seq(zrow, g_cn + (size_t)col * D_DIM);
            atomicMax(&sbest, pack_key(s, col));
        }
    } else {
        // overflow fallback (should not happen): exact scan of all codes,
        // same sequential per-dot order
        for (int col = tid; col < K_CODES; col += 128) {
            float s = dot_seq(zrow, g_cn + (size_t)col * D_DIM);
            atomicMax(&sbest, pack_key(s, col));
        }
    }
    __syncthreads();
    int idx = (int)(~(unsigned)sbest);

    float4 cv = ((const float4*)(g_cn + (size_t)idx * D_DIM))[tid];
    float4 zv = ((const float4*)zrow)[tid];
    ((float4*)(zq + (size_t)n * D_DIM))[tid] = cv;
    if (idx_out && tid == 0) idx_out[n] = (float)idx;

    if (do_loss) {
        float dx = cv.x - zv.x, dy = cv.y - zv.y, dz = cv.z - zv.z, dw = cv.w - zv.w;
        float ss = dx * dx + dy * dy + dz * dz + dw * dw;
        #pragma unroll
        for (int o = 16; o; o >>= 1) ss += __shfl_xor_sync(0xffffffffu, ss, o);
        if (l == 0) ws[w] = ss;
        __syncthreads();
        if (tid == 0) atomicAdd(&g_loss, ws[0] + ws[1] + ws[2] + ws[3]);
    }
}

__global__ void finalize_loss(float* __restrict__ loss_slot) {
    *loss_slot = 1.5f * g_loss / 16777216.0f;   // (beta+1) * mean, N*D = 2^24
}

// ---------------------------------------------------------------------------
extern "C" void kernel_launch(void* const* d_in, const int* in_sizes, int n_in,
                              void* d_out, int out_size) {
    const float* z = (const float*)d_in[0];
    const float* codebook = (const float*)d_in[1];
    float* out = (float*)d_out;

    const long long ND = (long long)N_ROWS * D_DIM;
    float* zq = out;
    float* idx_out   = (out_size >= ND + N_ROWS)     ? (out + ND) : nullptr;
    float* loss_slot = (out_size >= ND + N_ROWS + 1) ? (out + ND + N_ROWS) : nullptr;

    cudaFuncSetAttribute(gemm_screen,
                         cudaFuncAttributeMaxDynamicSharedMemorySize, SMEM_TOT);

    float *zn, *cn;
    __nv_bfloat16 *zb, *cb;
    cudaGetSymbolAddress((void**)&zn, g_zn);
    cudaGetSymbolAddress((void**)&cn, g_cn);
    cudaGetSymbolAddress((void**)&zb, g_zb);
    cudaGetSymbolAddress((void**)&cb, g_cb);

    init_kernel<<<(N_ROWS + 255) / 256, 256>>>();
    normalize_rows<<<N_ROWS, 128>>>(z, zn, zb);
    normalize_rows<<<K_CODES, 128>>>(codebook, cn, cb);
    gemm_screen<<<N_ROWS / 128, 512, SMEM_TOT>>>();
    finalize_rows<<<N_ROWS, 128>>>(zq, idx_out, loss_slot != nullptr);
    if (loss_slot) finalize_loss<<<1, 1>>>(loss_slot);
}

// round 7
// speedup vs baseline: 4.6220x; 1.0687x over previous
#include <cuda_runtime.h>
#include <cuda_bf16.h>
#include <cstdint>

#define N_ROWS  32768
#define D_DIM   512
#define K_CODES 8192
#define CAP     64
// Worst-case bf16 screening error bound: 2 * 2^-8 = 7.8e-3. EPS must exceed it.
#define EPS_MARGIN 1.25e-2f

// ---------------------------------------------------------------------------
// Device scratch
// ---------------------------------------------------------------------------
__device__ float          g_zn[N_ROWS  * D_DIM];   // 64 MB normalized z (fp32)
__device__ float          g_cn[K_CODES * D_DIM];   // 16 MB normalized codebook (fp32)
__device__ __nv_bfloat16  g_zb[N_ROWS  * D_DIM];   // 32 MB bf16 zn
__device__ __nv_bfloat16  g_cb[K_CODES * D_DIM];   //  8 MB bf16 cn
__device__ int            g_cand[N_ROWS][CAP];     //  8 MB candidate cols
__device__ int            g_candcnt[N_ROWS];
__device__ float          g_loss;

// ---------------------------------------------------------------------------
// Helpers
// ---------------------------------------------------------------------------
__device__ __forceinline__ uint32_t smem_u32(const void* p) {
    uint32_t a;
    asm("{ .reg .u64 t; cvta.to.shared.u64 t, %1; cvt.u32.u64 %0, t; }"
        : "=r"(a) : "l"(p));
    return a;
}
#define SWZ(o) ((o) ^ (((o) >> 3) & 0x70))

__device__ __forceinline__ void cp_async16(uint32_t dst, const void* src) {
    asm volatile("cp.async.cg.shared.global [%0], [%1], 16;"
                 :: "r"(dst), "l"(src) : "memory");
}
#define CP_COMMIT() asm volatile("cp.async.commit_group;" ::: "memory")
#define CP_WAIT1()  asm volatile("cp.async.wait_group 1;" ::: "memory")

__device__ __forceinline__ void ldsm_x4(uint32_t* r, uint32_t addr) {
    asm volatile("ldmatrix.sync.aligned.m8n8.x4.shared.b16 {%0,%1,%2,%3}, [%4];"
                 : "=r"(r[0]), "=r"(r[1]), "=r"(r[2]), "=r"(r[3]) : "r"(addr));
}
__device__ __forceinline__ void mma_bf16(float* c, const uint32_t* a,
                                         uint32_t b0, uint32_t b1) {
    asm volatile(
        "mma.sync.aligned.m16n8k16.row.col.f32.bf16.bf16.f32 "
        "{%0,%1,%2,%3}, {%4,%5,%6,%7}, {%8,%9}, {%0,%1,%2,%3};"
        : "+f"(c[0]), "+f"(c[1]), "+f"(c[2]), "+f"(c[3])
        : "r"(a[0]), "r"(a[1]), "r"(a[2]), "r"(a[3]), "r"(b0), "r"(b1));
}

// monotone float <-> uint (order-preserving)
__device__ __forceinline__ uint32_t mono(float v) {
    uint32_t u = __float_as_uint(v);
    return (u & 0x80000000u) ? ~u : (u | 0x80000000u);
}
__device__ __forceinline__ float unmono(uint32_t u) {
    return __uint_as_float((u & 0x80000000u) ? (u & 0x7fffffffu) : ~u);
}
__device__ __forceinline__ unsigned long long pack_key(float v, int col) {
    return ((unsigned long long)mono(v) << 32) | (unsigned)(~col);
}

// Sequential-order exact fp32 dot: single accumulator, k ascending (matches
// the R1 kernel whose indices agreed with the reference on every row).
__device__ __forceinline__ float dot_seq(const float* __restrict__ a,
                                         const float* __restrict__ b) {
    float s = 0.0f;
    #pragma unroll 16
    for (int q = 0; q < D_DIM / 4; ++q) {
        float4 av = ((const float4*)a)[q];
        float4 bv = ((const float4*)b)[q];
        s = fmaf(av.x, bv.x, s);
        s = fmaf(av.y, bv.y, s);
        s = fmaf(av.z, bv.z, s);
        s = fmaf(av.w, bv.w, s);
    }
    return s;
}

// ---------------------------------------------------------------------------
__global__ void init_kernel() {
    int i = blockIdx.x * blockDim.x + threadIdx.x;
    if (i < N_ROWS) g_candcnt[i] = 0;
    if (i == 0) g_loss = 0.0f;
}

// Row L2-normalize -> fp32 + bf16. One block (128 thr) per row.
__global__ void normalize_rows(const float* __restrict__ in,
                               float* __restrict__ out_f,
                               __nv_bfloat16* __restrict__ out_b) {
    int row = blockIdx.x;
    float4 v = ((const float4*)(in + (size_t)row * D_DIM))[threadIdx.x];
    float ss = v.x * v.x + v.y * v.y + v.z * v.z + v.w * v.w;
    #pragma unroll
    for (int o = 16; o; o >>= 1) ss += __shfl_xor_sync(0xffffffffu, ss, o);
    __shared__ float ws[4];
    if ((threadIdx.x & 31) == 0) ws[threadIdx.x >> 5] = ss;
    __syncthreads();
    float inv = 1.0f / fmaxf(sqrtf(ws[0] + ws[1] + ws[2] + ws[3]), 1e-12f);
    float4 o4 = make_float4(v.x * inv, v.y * inv, v.z * inv, v.w * inv);
    ((float4*)(out_f + (size_t)row * D_DIM))[threadIdx.x] = o4;
    __nv_bfloat162 b0 = __floats2bfloat162_rn(o4.x, o4.y);
    __nv_bfloat162 b1 = __floats2bfloat162_rn(o4.z, o4.w);
    ((uint2*)(out_b + (size_t)row * D_DIM))[threadIdx.x] =
        make_uint2(*(uint32_t*)&b0, *(uint32_t*)&b1);
}

// ---------------------------------------------------------------------------
// HMMA bf16 screening GEMM + prefix-max candidate collection.
// CTA tile 128 rows x 256 cols, 256 threads (8 warps, 2x4), warp tile 64x64.
// A (128x512 bf16, chunk-major [8][128][64]) resident in SMEM.
// B: 3-stage ring of 32KB chunks (256 codes x 64 k), prefetch distance 2,
// ONE __syncthreads per chunk. 32 N-tiles x 8 k-chunks = 256 iterations.
// ---------------------------------------------------------------------------
#define SMEM_A    0           // 8 chunks * 16384 = 131072
#define SMEM_B    131072      // 3 stages * 32768 = 98304
#define SMEM_RMAX 229376      // 128 * 4 = 512
#define SMEM_TOT  229888

__device__ __forceinline__ void prefetch_b(uint32_t sb, int cg, int tid) {
    const int nt = cg >> 3, c = cg & 7;
    const uint32_t dstb = sb + SMEM_B + (cg % 3) * 32768;
    #pragma unroll
    for (int it = 0; it < 8; ++it) {
        int u = tid + it * 256;             // 0..2047 16B units
        int r = u >> 3, cu = u & 7;         // code row 0..255
        cp_async16(dstb + SWZ(r * 128 + cu * 16),
                   &g_cb[(size_t)(nt * 256 + r) * D_DIM + c * 64 + cu * 8]);
    }
}

__global__ __launch_bounds__(256, 1) void gemm_screen() {
    extern __shared__ char smem[];
    const uint32_t sb = smem_u32(smem);
    const int tid = threadIdx.x;
    const int lane = tid & 31;
    const int wid = tid >> 5;
    const int warpM = wid >> 2;      // 0..1  (64 rows each)
    const int warpN = wid & 3;       // 0..3  (64 cols each)
    const int rowBase = blockIdx.x * 128;
    uint32_t* srunmax = (uint32_t*)(smem + SMEM_RMAX);

    if (tid < 128) srunmax[tid] = 0u;   // mono(-inf)

    // Group 0: resident A (128 rows x 512 bf16, chunk-major, swizzled)
    #pragma unroll
    for (int it = 0; it < 32; ++it) {
        int u = tid + it * 256;             // 0..8191 16B-units
        int c  = u >> 10;                   // k-chunk
        int r  = (u >> 3) & 127;
        int cu = u & 7;                     // 16B unit in row
        cp_async16(sb + SMEM_A + c * 16384 + SWZ(r * 128 + cu * 16),
                   &g_zb[(size_t)(rowBase + r) * D_DIM + c * 64 + cu * 8]);
    }
    CP_COMMIT();

    // Stages 0,1 of B
    prefetch_b(sb, 0, tid); CP_COMMIT();
    prefetch_b(sb, 1, tid); CP_COMMIT();

    float acc[4][8][4];                 // 64 rows x 64 cols per warp

    const int ra = warpM * 64 + (lane & 15);
    const int ca = (lane >> 4);
    const int nb = warpN * 64 + (lane & 7) + ((lane >> 4) << 3);
    const int cb = (lane >> 3) & 1;

    for (int cg = 0; cg < 256; ++cg) {  // 32 tiles * 8 chunks
        const int nt = cg >> 3;
        const int c  = cg & 7;

        // stage cg's group is 2nd-from-newest => wait_group 1 drains it
        CP_WAIT1();
        __syncthreads();
        // safe: slot (cg+2)%3 == (cg-1)%3; all warps passed the barrier above,
        // so chunk cg-1 compute is complete everywhere before the overwrite.
        if (cg + 2 < 256) prefetch_b(sb, cg + 2, tid);
        CP_COMMIT();                    // uniform one-group-per-iter

        if (c == 0) {
            #pragma unroll
            for (int m = 0; m < 4; ++m)
                #pragma unroll
                for (int j = 0; j < 8; ++j)
                    #pragma unroll
                    for (int e = 0; e < 4; ++e) acc[m][j][e] = 0.0f;
        }

        const uint32_t Ab = sb + SMEM_A + c * 16384;
        const uint32_t Bb = sb + SMEM_B + (cg % 3) * 32768;

        #pragma unroll
        for (int s = 0; s < 4; ++s) {   // 4 k16-steps within the 64-k chunk
            uint32_t a[4][4], b4[4][4];
            #pragma unroll
            for (int m = 0; m < 4; ++m)
                ldsm_x4(a[m], Ab + SWZ((ra + m * 16) * 128 + (s * 2 + ca) * 16));
            #pragma unroll
            for (int q = 0; q < 4; ++q)
                ldsm_x4(b4[q], Bb + SWZ((nb + q * 16) * 128 + (s * 2 + cb) * 16));
            #pragma unroll
            for (int m = 0; m < 4; ++m)
                #pragma unroll
                for (int j = 0; j < 8; ++j)
                    mma_bf16(acc[m][j], a[m],
                             b4[j >> 1][(j & 1) * 2], b4[j >> 1][(j & 1) * 2 + 1]);
        }

        if (c == 7) {
            // ---- epilogue for tile nt: prefix-max + candidate emission ----
            const int g = lane >> 2, tg = lane & 3;
            #pragma unroll
            for (int m = 0; m < 4; ++m)
                #pragma unroll
                for (int h = 0; h < 2; ++h) {
                    int row = warpM * 64 + m * 16 + h * 8 + g;
                    float mx = -1e30f;
                    #pragma unroll
                    for (int j = 0; j < 8; ++j)
                        mx = fmaxf(mx, fmaxf(acc[m][j][h * 2], acc[m][j][h * 2 + 1]));
                    mx = fmaxf(mx, __shfl_xor_sync(0xffffffffu, mx, 1));
                    mx = fmaxf(mx, __shfl_xor_sync(0xffffffffu, mx, 2));
                    if (tg == 0) atomicMax(&srunmax[row], mono(mx));
                }
            __syncthreads();
            #pragma unroll
            for (int m = 0; m < 4; ++m)
                #pragma unroll
                for (int h = 0; h < 2; ++h) {
                    int row = warpM * 64 + m * 16 + h * 8 + g;
                    float thr = unmono(srunmax[row]) - EPS_MARGIN;
                    #pragma unroll
                    for (int j = 0; j < 8; ++j)
                        #pragma unroll
                        for (int e = 0; e < 2; ++e) {
                            float v = acc[m][j][h * 2 + e];
                            if (v >= thr) {
                                int col = nt * 256 + warpN * 64 + j * 8 + 2 * tg + e;
                                int pos = atomicAdd(&g_candcnt[rowBase + row], 1);
                                if (pos < CAP) g_cand[rowBase + row][pos] = col;
                            }
                        }
                }
        }
    }
}

// ---------------------------------------------------------------------------
// Exact fp32 rescoring of candidates + outputs + loss. One block per row.
// Rescore dots use the sequential ascending-k single-accumulator order that
// matched the reference argmax on every row in the R1 all-fp32 kernel.
// ---------------------------------------------------------------------------
__global__ void finalize_rows(float* __restrict__ zq, float* __restrict__ idx_out,
                              int do_loss) {
    const int n = blockIdx.x;
    const int tid = threadIdx.x;
    const int w = tid >> 5, l = tid & 31;
    __shared__ unsigned long long sbest;
    __shared__ float ws[4];
    if (tid == 0) sbest = 0ull;
    __syncthreads();

    const float* zrow = g_zn + (size_t)n * D_DIM;
    int cnt = g_candcnt[n];

    if (cnt <= CAP) {
        // one thread per candidate, sequential-order dot
        if (tid < cnt) {
            int col = g_cand[n][tid];
            float s = dot_seq(zrow, g_cn + (size_t)col * D_DIM);
            atomicMax(&sbest, pack_key(s, col));
        }
    } else {
        // overflow fallback (should not happen): exact scan of all codes,
        // same sequential per-dot order
        for (int col = tid; col < K_CODES; col += 128) {
            float s = dot_seq(zrow, g_cn + (size_t)col * D_DIM);
            atomicMax(&sbest, pack_key(s, col));
        }
    }
    __syncthreads();
    int idx = (int)(~(unsigned)sbest);

    float4 cv = ((const float4*)(g_cn + (size_t)idx * D_DIM))[tid];
    float4 zv = ((const float4*)zrow)[tid];
    ((float4*)(zq + (size_t)n * D_DIM))[tid] = cv;
    if (idx_out && tid == 0) idx_out[n] = (float)idx;

    if (do_loss) {
        float dx = cv.x - zv.x, dy = cv.y - zv.y, dz = cv.z - zv.z, dw = cv.w - zv.w;
        float ss = dx * dx + dy * dy + dz * dz + dw * dw;
        #pragma unroll
        for (int o = 16; o; o >>= 1) ss += __shfl_xor_sync(0xffffffffu, ss, o);
        if (l == 0) ws[w] = ss;
        __syncthreads();
        if (tid == 0) atomicAdd(&g_loss, ws[0] + ws[1] + ws[2] + ws[3]);
    }
}

__global__ void finalize_loss(float* __restrict__ loss_slot) {
    *loss_slot = 1.5f * g_loss / 16777216.0f;   // (beta+1) * mean, N*D = 2^24
}

// ---------------------------------------------------------------------------
extern "C" void kernel_launch(void* const* d_in, const int* in_sizes, int n_in,
                              void* d_out, int out_size) {
    const float* z = (const float*)d_in[0];
    const float* codebook = (const float*)d_in[1];
    float* out = (float*)d_out;

    const long long ND = (long long)N_ROWS * D_DIM;
    float* zq = out;
    float* idx_out   = (out_size >= ND + N_ROWS)     ? (out + ND) : nullptr;
    float* loss_slot = (out_size >= ND + N_ROWS + 1) ? (out + ND + N_ROWS) : nullptr;

    cudaFuncSetAttribute(gemm_screen,
                         cudaFuncAttributeMaxDynamicSharedMemorySize, SMEM_TOT);

    float *zn, *cn;
    __nv_bfloat16 *zb, *cb;
    cudaGetSymbolAddress((void**)&zn, g_zn);
    cudaGetSymbolAddress((void**)&cn, g_cn);
    cudaGetSymbolAddress((void**)&zb, g_zb);
    cudaGetSymbolAddress((void**)&cb, g_cb);

    init_kernel<<<(N_ROWS + 255) / 256, 256>>>();
    normalize_rows<<<N_ROWS, 128>>>(z, zn, zb);
    normalize_rows<<<K_CODES, 128>>>(codebook, cn, cb);
    gemm_screen<<<N_ROWS / 128, 256, SMEM_TOT>>>();
    finalize_rows<<<N_ROWS, 128>>>(zq, idx_out, loss_slot != nullptr);
    if (loss_slot) finalize_loss<<<1, 1>>>(loss_slot);
}